// round 9
// baseline (speedup 1.0000x reference)
#include <cuda_runtime.h>
#include <cuda_bf16.h>
#include <cstdint>

#define B_  4
#define S_  2048
#define D_  1024
#define H_  16
#define HD_ 64
#define M_TOT (B_*S_)     // 8192
#define NQKV  3072
#define KDIM  1024

// ---------------------------------------------------------------------------
// Device scratch (all bf16 hi/lo pairs)
// ---------------------------------------------------------------------------
__device__ __nv_bfloat16 g_xhi[(size_t)M_TOT*KDIM];
__device__ __nv_bfloat16 g_xlo[(size_t)M_TOT*KDIM];
__device__ __nv_bfloat16 g_wqkv_hi[(size_t)NQKV*KDIM];   // [n][k] K-major
__device__ __nv_bfloat16 g_wqkv_lo[(size_t)NQKV*KDIM];
__device__ __nv_bfloat16 g_wo_hi[(size_t)D_*KDIM];
__device__ __nv_bfloat16 g_wo_lo[(size_t)D_*KDIM];
__device__ __nv_bfloat16 g_qhi[(size_t)B_*H_*S_*HD_];    // [b,h,s,e], Q pre-scaled
__device__ __nv_bfloat16 g_qlo[(size_t)B_*H_*S_*HD_];
__device__ __nv_bfloat16 g_khi[(size_t)B_*H_*S_*HD_];
__device__ __nv_bfloat16 g_klo[(size_t)B_*H_*S_*HD_];
__device__ __nv_bfloat16 g_vhi[(size_t)B_*H_*S_*HD_];
__device__ __nv_bfloat16 g_vlo[(size_t)B_*H_*S_*HD_];
__device__ __nv_bfloat16 g_aohi[(size_t)M_TOT*KDIM];     // attention out [m][k]
__device__ __nv_bfloat16 g_aolo[(size_t)M_TOT*KDIM];

// ---------------------------------------------------------------------------
// Portable PTX helpers (sm_80+ ISA only)
// ---------------------------------------------------------------------------
__device__ __forceinline__ uint32_t smem_u32(const void* p) {
    uint32_t a;
    asm("{ .reg .u64 t; cvta.to.shared.u64 t, %1; cvt.u32.u64 %0, t; }"
        : "=r"(a) : "l"(p));
    return a;
}

__device__ __forceinline__ void cp16(uint32_t dst, const void* src) {
    asm volatile("cp.async.cg.shared.global [%0], [%1], 16;"
                 :: "r"(dst), "l"(src) : "memory");
}
#define CP_COMMIT() asm volatile("cp.async.commit_group;" ::: "memory")
#define CP_WAIT1()  asm volatile("cp.async.wait_group 1;"  ::: "memory")

__device__ __forceinline__ void ldsm4(uint32_t& r0, uint32_t& r1,
                                      uint32_t& r2, uint32_t& r3, uint32_t addr) {
    asm volatile("ldmatrix.sync.aligned.m8n8.x4.shared.b16 {%0,%1,%2,%3}, [%4];"
                 : "=r"(r0), "=r"(r1), "=r"(r2), "=r"(r3) : "r"(addr));
}
__device__ __forceinline__ void ldsm4t(uint32_t& r0, uint32_t& r1,
                                       uint32_t& r2, uint32_t& r3, uint32_t addr) {
    asm volatile("ldmatrix.sync.aligned.m8n8.x4.trans.shared.b16 {%0,%1,%2,%3}, [%4];"
                 : "=r"(r0), "=r"(r1), "=r"(r2), "=r"(r3) : "r"(addr));
}

__device__ __forceinline__ void mma16816(float* c,
                                         uint32_t a0, uint32_t a1, uint32_t a2, uint32_t a3,
                                         uint32_t b0, uint32_t b1) {
    asm volatile(
        "mma.sync.aligned.m16n8k16.row.col.f32.bf16.bf16.f32 "
        "{%0,%1,%2,%3}, {%4,%5,%6,%7}, {%8,%9}, {%0,%1,%2,%3};"
        : "+f"(c[0]), "+f"(c[1]), "+f"(c[2]), "+f"(c[3])
        : "r"(a0), "r"(a1), "r"(a2), "r"(a3), "r"(b0), "r"(b1));
}

__device__ __forceinline__ void split_bf16(float v, __nv_bfloat16& hi, __nv_bfloat16& lo) {
    hi = __float2bfloat16(v);
    lo = __float2bfloat16(v - __bfloat162float(hi));
}
__device__ __forceinline__ uint32_t pack2(__nv_bfloat16 a, __nv_bfloat16 b) {
    __nv_bfloat162 t; t.x = a; t.y = b;
    return *(uint32_t*)&t;
}

// ---------------------------------------------------------------------------
// Conversion kernels
// ---------------------------------------------------------------------------
__global__ void conv_x_kernel(const float* __restrict__ src) {
    size_t i = ((size_t)blockIdx.x * 256 + threadIdx.x) * 4;
    float4 v = *(const float4*)(src + i);
    __nv_bfloat16 h, l;
    split_bf16(v.x, h, l); g_xhi[i+0] = h; g_xlo[i+0] = l;
    split_bf16(v.y, h, l); g_xhi[i+1] = h; g_xlo[i+1] = l;
    split_bf16(v.z, h, l); g_xhi[i+2] = h; g_xlo[i+2] = l;
    split_bf16(v.w, h, l); g_xhi[i+3] = h; g_xlo[i+3] = l;
}

__global__ void conv_wo_kernel(const float* __restrict__ src) {
    size_t i = ((size_t)blockIdx.x * 256 + threadIdx.x) * 4;
    float4 v = *(const float4*)(src + i);
    __nv_bfloat16 h, l;
    split_bf16(v.x, h, l); g_wo_hi[i+0] = h; g_wo_lo[i+0] = l;
    split_bf16(v.y, h, l); g_wo_hi[i+1] = h; g_wo_lo[i+1] = l;
    split_bf16(v.z, h, l); g_wo_hi[i+2] = h; g_wo_lo[i+2] = l;
    split_bf16(v.w, h, l); g_wo_hi[i+3] = h; g_wo_lo[i+3] = l;
}

__global__ void conv_wqkv_kernel(const float* __restrict__ Wq,
                                 const float* __restrict__ Wk,
                                 const float* __restrict__ Wv) {
    __shared__ float t[64][65];
    const int p = blockIdx.z, h = blockIdx.y, d0 = blockIdx.x * 64;
    const float* W = (p == 0) ? Wq : ((p == 1) ? Wk : Wv);
    const float* Wh = W + (size_t)h * D_ * HD_;
    const int tid = threadIdx.x;
#pragma unroll
    for (int j = 0; j < 16; j++) {
        int idx = tid + j * 256;
        int d = idx >> 6, e = idx & 63;
        t[d][e] = Wh[(size_t)(d0 + d) * HD_ + e];
    }
    __syncthreads();
#pragma unroll
    for (int j = 0; j < 16; j++) {
        int idx = tid + j * 256;
        int e = idx >> 6, d = idx & 63;
        float v = t[d][e];
        __nv_bfloat16 hi, lo;
        split_bf16(v, hi, lo);
        size_t out = (size_t)(p * 1024 + h * 64 + e) * KDIM + d0 + d;
        g_wqkv_hi[out] = hi;
        g_wqkv_lo[out] = lo;
    }
}

// ---------------------------------------------------------------------------
// bf16x3 GEMM via mma.sync.m16n8k16.
// R8: TERM-MAJOR MMA order — 8 independent MMAs per term group so dependent
// ops to the same accumulator are ~8 issues apart (covers HMMA latency).
// Per-accumulator arithmetic order unchanged (hh, hl, lh per k-step).
// ---------------------------------------------------------------------------
#define ARR_B     18432           // 128 rows x 144B (64 bf16 + 16B pad)
#define STAGE_B   (4 * ARR_B)     // Ahi, Alo, Bhi, Blo = 73728
#define GEMM_SMEM (3 * STAGE_B)   // 221184
#define NCHUNK    16              // K = 1024 / 64

__global__ __launch_bounds__(512)
void gemm_mma(float* __restrict__ outp, const float* __restrict__ bias, int mode) {
    extern __shared__ __align__(128) char smem[];
    const uint32_t sb = smem_u32(smem);
    const int tid = threadIdx.x;
    const int warp = tid >> 5, lane = tid & 31;
    const int wm = warp >> 2, wn = warp & 3;     // 4x4 warp grid, 32x32 tiles
    const int m0 = blockIdx.y * 128, n0 = blockIdx.x * 128;

    const __nv_bfloat16* Ahi = mode ? g_aohi : g_xhi;
    const __nv_bfloat16* Alo = mode ? g_aolo : g_xlo;
    const __nv_bfloat16* Bhi = mode ? g_wo_hi : g_wqkv_hi;
    const __nv_bfloat16* Blo = mode ? g_wo_lo : g_wqkv_lo;

    const int r0_ = tid >> 3, c0_ = tid & 7;
    const int r1_ = (tid + 512) >> 3, c1_ = tid & 7;
    const size_t gA0 = (size_t)(m0 + r0_) * KDIM + c0_ * 8;
    const size_t gA1 = (size_t)(m0 + r1_) * KDIM + c1_ * 8;
    const size_t gB0 = (size_t)(n0 + r0_) * KDIM + c0_ * 8;
    const size_t gB1 = (size_t)(n0 + r1_) * KDIM + c1_ * 8;
    const uint32_t so0 = (uint32_t)r0_ * 144 + (uint32_t)c0_ * 16;
    const uint32_t so1 = (uint32_t)r1_ * 144 + (uint32_t)c1_ * 16;

#define LOAD_STAGE(st, kel) do { \
    uint32_t b_ = sb + (uint32_t)(st) * STAGE_B; \
    cp16(b_ +             so0, Ahi + gA0 + (kel)); \
    cp16(b_ +             so1, Ahi + gA1 + (kel)); \
    cp16(b_ +     ARR_B + so0, Alo + gA0 + (kel)); \
    cp16(b_ +     ARR_B + so1, Alo + gA1 + (kel)); \
    cp16(b_ + 2 * ARR_B + so0, Bhi + gB0 + (kel)); \
    cp16(b_ + 2 * ARR_B + so1, Bhi + gB1 + (kel)); \
    cp16(b_ + 3 * ARR_B + so0, Blo + gB0 + (kel)); \
    cp16(b_ + 3 * ARR_B + so1, Blo + gB1 + (kel)); \
} while (0)

    LOAD_STAGE(0, 0);  CP_COMMIT();
    LOAD_STAGE(1, 64); CP_COMMIT();

    const uint32_t aoff = (uint32_t)(wm * 32 + (lane & 15)) * 144 + (uint32_t)(lane >> 4) * 16;
    const uint32_t boff = (uint32_t)(wn * 32 + (lane & 7) + ((lane >> 4) & 1) * 8) * 144
                        + (uint32_t)((lane >> 3) & 1) * 16;

    float c[2][4][4];
#pragma unroll
    for (int i = 0; i < 2; i++)
#pragma unroll
        for (int j = 0; j < 4; j++)
#pragma unroll
            for (int r = 0; r < 4; r++) c[i][j][r] = 0.f;

    for (int ck = 0; ck < NCHUNK; ck++) {
        CP_WAIT1();
        __syncthreads();
        const uint32_t base = sb + (uint32_t)(ck % 3) * STAGE_B;
        if (ck + 2 < NCHUNK) LOAD_STAGE((ck + 2) % 3, (size_t)(ck + 2) * 64);
        CP_COMMIT();

#pragma unroll
        for (int kk = 0; kk < 4; kk++) {
            uint32_t ah[2][4], al[2][4], bh[4][2], bl[4][2];
#pragma unroll
            for (int i = 0; i < 2; i++) {
                ldsm4(ah[i][0], ah[i][1], ah[i][2], ah[i][3],
                      base + aoff + i * 2304 + kk * 32);
                ldsm4(al[i][0], al[i][1], al[i][2], al[i][3],
                      base + ARR_B + aoff + i * 2304 + kk * 32);
            }
#pragma unroll
            for (int p = 0; p < 2; p++) {
                uint32_t r0, r1, r2, r3;
                ldsm4(r0, r1, r2, r3, base + 2 * ARR_B + boff + p * 2304 + kk * 32);
                bh[2*p][0] = r0; bh[2*p][1] = r1; bh[2*p+1][0] = r2; bh[2*p+1][1] = r3;
                ldsm4(r0, r1, r2, r3, base + 3 * ARR_B + boff + p * 2304 + kk * 32);
                bl[2*p][0] = r0; bl[2*p][1] = r1; bl[2*p+1][0] = r2; bl[2*p+1][1] = r3;
            }
            // term hh — 8 independent MMAs
#pragma unroll
            for (int i = 0; i < 2; i++)
#pragma unroll
                for (int j = 0; j < 4; j++)
                    mma16816(c[i][j], ah[i][0], ah[i][1], ah[i][2], ah[i][3],
                             bh[j][0], bh[j][1]);
            // term hl
#pragma unroll
            for (int i = 0; i < 2; i++)
#pragma unroll
                for (int j = 0; j < 4; j++)
                    mma16816(c[i][j], ah[i][0], ah[i][1], ah[i][2], ah[i][3],
                             bl[j][0], bl[j][1]);
            // term lh
#pragma unroll
            for (int i = 0; i < 2; i++)
#pragma unroll
                for (int j = 0; j < 4; j++)
                    mma16816(c[i][j], al[i][0], al[i][1], al[i][2], al[i][3],
                             bh[j][0], bh[j][1]);
        }
    }

#pragma unroll
    for (int i = 0; i < 2; i++) {
#pragma unroll
        for (int j = 0; j < 4; j++) {
            const int ncol = n0 + wn * 32 + j * 8 + (lane & 3) * 2;
#pragma unroll
            for (int half = 0; half < 2; half++) {
                const int row = m0 + wm * 32 + i * 16 + (lane >> 2) + half * 8;
                float vx = c[i][j][half * 2], vy = c[i][j][half * 2 + 1];
                if (mode == 0) {
                    const int p = ncol >> 10;
                    const float sc = (p == 0) ? 0.125f : 1.0f;
                    __nv_bfloat16* Th = (p == 0) ? g_qhi : ((p == 1) ? g_khi : g_vhi);
                    __nv_bfloat16* Tl = (p == 0) ? g_qlo : ((p == 1) ? g_klo : g_vlo);
                    const int h = (ncol & 1023) >> 6;
                    const int e = ncol & 63;
                    const int bb = row >> 11, ss = row & 2047;
                    __nv_bfloat16 hx, lx, hy, ly;
                    split_bf16(vx * sc, hx, lx);
                    split_bf16(vy * sc, hy, ly);
                    const size_t off = ((size_t)(bb * H_ + h) * S_ + ss) * HD_ + e;
                    *(uint32_t*)(Th + off) = pack2(hx, hy);
                    *(uint32_t*)(Tl + off) = pack2(lx, ly);
                } else {
                    float2 bv = *(const float2*)(bias + ncol);
                    float2 v = make_float2(vx + bv.x, vy + bv.y);
                    *(float2*)(outp + (size_t)row * D_ + ncol) = v;
                }
            }
        }
    }
#undef LOAD_STAGE
}

// ---------------------------------------------------------------------------
// Tensor-core causal flash attention.
// R8: term-major MMA order in both GEMMs (frags for all 4 nb pre-loaded per
// ks-step). Per-accumulator arithmetic order unchanged.
// ---------------------------------------------------------------------------
#define AT_LDB  144
#define AT_KSZ  (64 * AT_LDB)
#define AT_STAGE (4 * AT_KSZ)
#define AT_Q    (2 * 128 * AT_LDB)
#define AT_SMEM (AT_Q + 2 * AT_STAGE)

__global__ __launch_bounds__(256, 1)
void attn_mma() {
    extern __shared__ __align__(128) char smc[];
    const uint32_t sb = smem_u32(smc);
    const int tid = threadIdx.x;
    const int warp = tid >> 5, lane = tid & 31;
    const int bq = blockIdx.x, bh = blockIdx.y;
    const int q0 = bq * 128;

    const __nv_bfloat16* Qh = g_qhi + (size_t)bh * S_ * HD_;
    const __nv_bfloat16* Ql = g_qlo + (size_t)bh * S_ * HD_;
    const __nv_bfloat16* Kh = g_khi + (size_t)bh * S_ * HD_;
    const __nv_bfloat16* Kl = g_klo + (size_t)bh * S_ * HD_;
    const __nv_bfloat16* Vh = g_vhi + (size_t)bh * S_ * HD_;
    const __nv_bfloat16* Vl = g_vlo + (size_t)bh * S_ * HD_;

#pragma unroll
    for (int i = 0; i < 4; i++) {
        int idx = tid + i * 256;
        int r = idx >> 3, ch = idx & 7;
        size_t g = (size_t)(q0 + r) * HD_ + ch * 8;
        cp16(sb + r * AT_LDB + ch * 16, Qh + g);
        cp16(sb + 128 * AT_LDB + r * AT_LDB + ch * 16, Ql + g);
    }
    CP_COMMIT();

    const int ktmax = 2 * bq + 1;

#define LOAD_KV(kt, st) do { \
    uint32_t kb_ = sb + AT_Q + (uint32_t)(st) * AT_STAGE; \
    int t0_ = (kt) * 64; \
    _Pragma("unroll") \
    for (int i_ = 0; i_ < 2; i_++) { \
        int idx_ = tid + i_ * 256; \
        int r_ = idx_ >> 3, ch_ = idx_ & 7; \
        size_t g_ = (size_t)(t0_ + r_) * HD_ + ch_ * 8; \
        uint32_t s_ = (uint32_t)r_ * AT_LDB + (uint32_t)ch_ * 16; \
        cp16(kb_ + s_,              Kh + g_); \
        cp16(kb_ +     AT_KSZ + s_, Kl + g_); \
        cp16(kb_ + 2 * AT_KSZ + s_, Vh + g_); \
        cp16(kb_ + 3 * AT_KSZ + s_, Vl + g_); \
    } } while (0)

    LOAD_KV(0, 0); CP_COMMIT();
    CP_WAIT1();
    __syncthreads();

    uint32_t qh[4][4], ql[4][4];
    const uint32_t aoff = (uint32_t)(warp * 16 + (lane & 15)) * AT_LDB
                        + (uint32_t)(lane >> 4) * 16;
#pragma unroll
    for (int ks = 0; ks < 4; ks++) {
        ldsm4(qh[ks][0], qh[ks][1], qh[ks][2], qh[ks][3], sb + aoff + ks * 32);
        ldsm4(ql[ks][0], ql[ks][1], ql[ks][2], ql[ks][3],
              sb + 128 * AT_LDB + aoff + ks * 32);
    }
    if (1 <= ktmax) LOAD_KV(1, 1);
    CP_COMMIT();

    float oacc[8][4];
#pragma unroll
    for (int j = 0; j < 8; j++)
#pragma unroll
        for (int r = 0; r < 4; r++) oacc[j][r] = 0.f;
    float mrow[2] = {-1e30f, -1e30f};
    float lrow[2] = {0.f, 0.f};

    const int rg = q0 + warp * 16 + (lane >> 2);

    for (int kt = 0; kt <= ktmax; kt++) {
        CP_WAIT1();
        __syncthreads();
        const uint32_t kb = sb + AT_Q + (uint32_t)(kt & 1) * AT_STAGE;

        float sfr[8][4];
#pragma unroll
        for (int j = 0; j < 8; j++)
#pragma unroll
            for (int r = 0; r < 4; r++) sfr[j][r] = 0.f;

        // ---- S = Q K^T (bf16x3, term-major) ----
#pragma unroll
        for (int ks = 0; ks < 4; ks++) {
            uint32_t kh_[4][4], kl_[4][4];
#pragma unroll
            for (int nb = 0; nb < 4; nb++) {
                const uint32_t brow = (uint32_t)(nb * 16 + (lane & 7) + ((lane >> 4) & 1) * 8) * AT_LDB
                                    + (uint32_t)((lane >> 3) & 1) * 16;
                ldsm4(kh_[nb][0], kh_[nb][1], kh_[nb][2], kh_[nb][3],
                      kb + brow + ks * 32);
                ldsm4(kl_[nb][0], kl_[nb][1], kl_[nb][2], kl_[nb][3],
                      kb + AT_KSZ + brow + ks * 32);
            }
            // term hh
#pragma unroll
            for (int nb = 0; nb < 4; nb++) {
                mma16816(sfr[2*nb],   qh[ks][0], qh[ks][1], qh[ks][2], qh[ks][3],
                         kh_[nb][0], kh_[nb][1]);
                mma16816(sfr[2*nb+1], qh[ks][0], qh[ks][1], qh[ks][2], qh[ks][3],
                         kh_[nb][2], kh_[nb][3]);
            }
            // term hl
#pragma unroll
            for (int nb = 0; nb < 4; nb++) {
                mma16816(sfr[2*nb],   qh[ks][0], qh[ks][1], qh[ks][2], qh[ks][3],
                         kl_[nb][0], kl_[nb][1]);
                mma16816(sfr[2*nb+1], qh[ks][0], qh[ks][1], qh[ks][2], qh[ks][3],
                         kl_[nb][2], kl_[nb][3]);
            }
            // term lh
#pragma unroll
            for (int nb = 0; nb < 4; nb++) {
                mma16816(sfr[2*nb],   ql[ks][0], ql[ks][1], ql[ks][2], ql[ks][3],
                         kh_[nb][0], kh_[nb][1]);
                mma16816(sfr[2*nb+1], ql[ks][0], ql[ks][1], ql[ks][2], ql[ks][3],
                         kh_[nb][2], kh_[nb][3]);
            }
        }

        if (kt >= 2 * bq) {
            const int c0 = kt * 64 + (lane & 3) * 2;
#pragma unroll
            for (int j = 0; j < 8; j++) {
                const int c = c0 + j * 8;
                if (c     > rg)     sfr[j][0] = -1e30f;
                if (c + 1 > rg)     sfr[j][1] = -1e30f;
                if (c     > rg + 8) sfr[j][2] = -1e30f;
                if (c + 1 > rg + 8) sfr[j][3] = -1e30f;
            }
        }

#pragma unroll
        for (int r = 0; r < 2; r++) {
            float mx = -1e30f;
#pragma unroll
            for (int j = 0; j < 8; j++)
                mx = fmaxf(mx, fmaxf(sfr[j][2*r], sfr[j][2*r+1]));
            mx = fmaxf(mx, __shfl_xor_sync(0xffffffffu, mx, 1));
            mx = fmaxf(mx, __shfl_xor_sync(0xffffffffu, mx, 2));
            const float mnew = fmaxf(mrow[r], mx);
            const float corr = __expf(mrow[r] - mnew);
            mrow[r] = mnew;
            float sum = 0.f;
#pragma unroll
            for (int j = 0; j < 8; j++) {
                sfr[j][2*r]   = __expf(sfr[j][2*r]   - mnew);
                sfr[j][2*r+1] = __expf(sfr[j][2*r+1] - mnew);
                sum += sfr[j][2*r] + sfr[j][2*r+1];
            }
            sum += __shfl_xor_sync(0xffffffffu, sum, 1);
            sum += __shfl_xor_sync(0xffffffffu, sum, 2);
            lrow[r] = lrow[r] * corr + sum;
#pragma unroll
            for (int j = 0; j < 8; j++) {
                oacc[j][2*r]   *= corr;
                oacc[j][2*r+1] *= corr;
            }
        }

        uint32_t ph[4][4], pl[4][4];
#pragma unroll
        for (int ks = 0; ks < 4; ks++) {
#pragma unroll
            for (int idx = 0; idx < 4; idx++) {
                const float a = sfr[2*ks + (idx >> 1)][(idx & 1) * 2];
                const float b = sfr[2*ks + (idx >> 1)][(idx & 1) * 2 + 1];
                __nv_bfloat16 ahB, alB, bhB, blB;
                split_bf16(a, ahB, alB);
                split_bf16(b, bhB, blB);
                ph[ks][idx] = pack2(ahB, bhB);
                pl[ks][idx] = pack2(alB, blB);
            }
        }

        // ---- O += P V (bf16x3, term-major) ----
        const uint32_t vb = kb + 2 * AT_KSZ;
#pragma unroll
        for (int ks = 0; ks < 4; ks++) {
            const uint32_t vrow = (uint32_t)(ks * 16 + (lane & 15)) * AT_LDB
                                + (uint32_t)(lane >> 4) * 16;
            uint32_t vh_[4][4], vl_[4][4];
#pragma unroll
            for (int nb = 0; nb < 4; nb++) {
                ldsm4t(vh_[nb][0], vh_[nb][1], vh_[nb][2], vh_[nb][3],
                       vb + vrow + nb * 32);
                ldsm4t(vl_[nb][0], vl_[nb][1], vl_[nb][2], vl_[nb][3],
                       vb + AT_KSZ + vrow + nb * 32);
            }
            // term hh
#pragma unroll
            for (int nb = 0; nb < 4; nb++) {
                mma16816(oacc[2*nb],   ph[ks][0], ph[ks][1], ph[ks][2], ph[ks][3],
                         vh_[nb][0], vh_[nb][1]);
                mma16816(oacc[2*nb+1], ph[ks][0], ph[ks][1], ph[ks][2], ph[ks][3],
                         vh_[nb][2], vh_[nb][3]);
            }
            // term hl
#pragma unroll
            for (int nb = 0; nb < 4; nb++) {
                mma16816(oacc[2*nb],   ph[ks][0], ph[ks][1], ph[ks][2], ph[ks][3],
                         vl_[nb][0], vl_[nb][1]);
                mma16816(oacc[2*nb+1], ph[ks][0], ph[ks][1], ph[ks][2], ph[ks][3],
                         vl_[nb][2], vl_[nb][3]);
            }
            // term lh
#pragma unroll
            for (int nb = 0; nb < 4; nb++) {
                mma16816(oacc[2*nb],   pl[ks][0], pl[ks][1], pl[ks][2], pl[ks][3],
                         vh_[nb][0], vh_[nb][1]);
                mma16816(oacc[2*nb+1], pl[ks][0], pl[ks][1], pl[ks][2], pl[ks][3],
                         vh_[nb][2], vh_[nb][3]);
            }
        }

        __syncthreads();
        if (kt + 2 <= ktmax) LOAD_KV(kt + 2, kt & 1);
        CP_COMMIT();
    }

    const int b = bh >> 4, h = bh & 15;
    const float inv0 = 1.0f / lrow[0];
    const float inv1 = 1.0f / lrow[1];
#pragma unroll
    for (int j = 0; j < 8; j++) {
        const int e = j * 8 + (lane & 3) * 2;
#pragma unroll
        for (int r = 0; r < 2; r++) {
            const float inv = r ? inv1 : inv0;
            const float vx = oacc[j][2*r]     * inv;
            const float vy = oacc[j][2*r + 1] * inv;
            __nv_bfloat16 hx, lx, hy, ly;
            split_bf16(vx, hx, lx);
            split_bf16(vy, hy, ly);
            const size_t off = (size_t)(b * S_ + rg + r * 8) * KDIM + h * 64 + e;
            *(uint32_t*)(g_aohi + off) = pack2(hx, hy);
            *(uint32_t*)(g_aolo + off) = pack2(lx, ly);
        }
    }
#undef LOAD_KV
}

// ---------------------------------------------------------------------------
extern "C" void kernel_launch(void* const* d_in, const int* in_sizes, int n_in,
                              void* d_out, int out_size) {
    const float* x  = (const float*)d_in[0];
    const float* Wq = (const float*)d_in[1];
    const float* Wk = (const float*)d_in[2];
    const float* Wv = (const float*)d_in[3];
    const float* Wo = (const float*)d_in[4];
    const float* bo = (const float*)d_in[5];
    float* out = (float*)d_out;

    cudaFuncSetAttribute(gemm_mma, cudaFuncAttributeMaxDynamicSharedMemorySize,
                         (int)GEMM_SMEM);
    cudaFuncSetAttribute(attn_mma, cudaFuncAttributeMaxDynamicSharedMemorySize,
                         (int)AT_SMEM);

    conv_x_kernel<<<(M_TOT * KDIM) / (256 * 4), 256>>>(x);
    conv_wqkv_kernel<<<dim3(16, 16, 3), 256>>>(Wq, Wk, Wv);
    conv_wo_kernel<<<(D_ * KDIM) / (256 * 4), 256>>>(Wo);

    gemm_mma<<<dim3(NQKV / 128, M_TOT / 128), 512, GEMM_SMEM>>>(nullptr, nullptr, 0);
    attn_mma<<<dim3(S_ / 128, B_ * H_), 256, AT_SMEM>>>();
    gemm_mma<<<dim3(D_ / 128, M_TOT / 128), 512, GEMM_SMEM>>>(out, bo, 1);
}